// round 6
// baseline (speedup 1.0000x reference)
#include <cuda_runtime.h>
#include <cuda_bf16.h>
#include <math.h>

// Problem constants
#define Bc   64
#define Lc   2048
#define Dc   128
#define Hc   4
#define Ac   128
#define Mc   16
#define Vc   100000
#define NNZc 262144
#define HDc  32
#define GAMMAc 0.3
#define BETAc  1.0

#define NBLK 148
#define NTHR 512

typedef unsigned long long ull;

#define FMA2(acc, a, b) asm("fma.rn.f32x2 %0, %1, %2, %0;" : "+l"(acc) : "l"(a), "l"(b))
__device__ __forceinline__ ull pack2(float x, float y) {
    ull d; asm("mov.b64 %0, {%1, %2};" : "=l"(d) : "f"(x), "f"(y)); return d;
}
__device__ __forceinline__ float2 unpack2(ull v) {
    float2 r; asm("mov.b64 {%0, %1}, %2;" : "=f"(r.x), "=f"(r.y) : "l"(v)); return r;
}

// ---------------- scratch (static __device__, no allocation) ----------------
__device__ __align__(16) float  g_sigT[(size_t)Vc * Mc];
__device__ __align__(16) float  g_PhiP[Mc * Ac];
__device__ double g_sizeP[Mc];
__device__ __align__(16) float  g_PhiQ[Bc * Ac];
__device__ double g_psum[Bc * Mc];
__device__ __align__(16) float  g_AQ[Bc * Ac];
__device__ __align__(16) float  g_BP[Mc * Ac];
__device__ __align__(16) float  g_Vp[Mc * HDc];
__device__ __align__(16) float  g_Z[Bc * HDc];
__device__ __align__(16) float  g_C[Bc * Dc * Hc];

// ---------------- grid barrier (sense-reversal, co-resident grid) ----------------
__device__ volatile unsigned g_barCnt;   // zero-init; returns to 0 after each barrier
__device__ volatile unsigned g_epoch;    // monotonic

__device__ __forceinline__ void grid_barrier() {
    __syncthreads();
    if (threadIdx.x == 0) {
        unsigned e = g_epoch;
        __threadfence();
        unsigned old = atomicAdd((unsigned*)&g_barCnt, 1u);
        if (old == gridDim.x - 1) {
            g_barCnt = 0;
            __threadfence();
            atomicAdd((unsigned*)&g_epoch, 1u);
        } else {
            while (g_epoch == e) { __nanosleep(64); }
        }
        __threadfence();
    }
    __syncthreads();
}

#define SSTR 18   // smem row stride for P1 (even -> 8B-aligned pair loads)

__global__ void __launch_bounds__(NTHR)
mega(const float* __restrict__ ts,
     const int*   __restrict__ qids,
     const int*   __restrict__ qoffs,
     const float* __restrict__ atom_emb,
     const float* __restrict__ phi_logits,
     const float* __restrict__ W_A,
     const float* __restrict__ W_B,
     const float* __restrict__ W_val,
     const float* __restrict__ b_val,
     const float* __restrict__ W_gate,
     const float* __restrict__ b_gate,
     const float* __restrict__ W_out,
     const float* __restrict__ b_out,
     const float* __restrict__ size_w,
     float* __restrict__ out) {
    __shared__ __align__(16) float sm[3200];   // P1: sS[1152] + sRed[2048]; P3b: sAttn[1024]
    float* sS0 = sm;                 // [2][32*SSTR]
    float* sRed = sm + 2 * 32 * SSTR;
    float* sAttn = sm;

    const int t = threadIdx.x;
    const int bid = blockIdx.x;
    const int w = t >> 5, lane = t & 31;

    // ================= P0: zero accumulators =================
    {
        int idx = bid * NTHR + t;
        int stride = NBLK * NTHR;
        for (int i = idx; i < Mc * Ac; i += stride) g_PhiP[i] = 0.f;
        for (int i = idx; i < Bc * Ac; i += stride) g_PhiQ[i] = 0.f;
        for (int i = idx; i < Mc; i += stride) g_sizeP[i] = 0.0;
        for (int i = idx; i < Bc * Mc; i += stride) g_psum[i] = 0.0;
    }
    grid_barrier();

    // ================= P1: vocab pass =================
    {
        const int mS = t >> 5, vS = t & 31;
        ull acc2[8][4];
#pragma unroll
        for (int mp = 0; mp < 8; mp++)
#pragma unroll
            for (int c = 0; c < 4; c++) acc2[mp][c] = pack2(0.f, 0.f);
        double szAcc = 0.0;

        const int nTiles = Vc / 32;   // 3125
        int gt = bid;
        // prologue
        {
            float x = phi_logits[(size_t)mS * Vc + gt * 32 + vS];
            float s = 1.0f / (1.0f + __expf(-x));
            sS0[0 * 32 * SSTR + vS * SSTR + mS] = s;
            szAcc += (double)s;
        }
        float4 eA = *reinterpret_cast<const float4*>(&atom_emb[((size_t)gt * 32 + w) * Ac + lane * 4]);
        float4 eB = *reinterpret_cast<const float4*>(&atom_emb[((size_t)gt * 32 + w + 16) * Ac + lane * 4]);
        __syncthreads();

        int cur = 0;
        for (; gt < nTiles; gt += NBLK) {
            const int gtn = gt + NBLK;
            const bool has = gtn < nTiles;
            float xn = 0.f; float4 eAn, eBn;
            if (has) {
                xn  = phi_logits[(size_t)mS * Vc + gtn * 32 + vS];
                eAn = *reinterpret_cast<const float4*>(&atom_emb[((size_t)gtn * 32 + w) * Ac + lane * 4]);
                eBn = *reinterpret_cast<const float4*>(&atom_emb[((size_t)gtn * 32 + w + 16) * Ac + lane * 4]);
            }
            // sigT writeout for current tile
            {
                int v2 = t >> 4, m2 = t & 15;
                g_sigT[((size_t)gt * 32 + v2) * 16 + m2] = sS0[cur * 32 * SSTR + v2 * SSTR + m2];
            }
            // FFMA2 accumulation
            {
                ull eDA[4], eDB[4];
                eDA[0] = pack2(eA.x, eA.x); eDA[1] = pack2(eA.y, eA.y);
                eDA[2] = pack2(eA.z, eA.z); eDA[3] = pack2(eA.w, eA.w);
                eDB[0] = pack2(eB.x, eB.x); eDB[1] = pack2(eB.y, eB.y);
                eDB[2] = pack2(eB.z, eB.z); eDB[3] = pack2(eB.w, eB.w);
                const ull* spA = reinterpret_cast<const ull*>(&sS0[cur * 32 * SSTR + w * SSTR]);
                const ull* spB = reinterpret_cast<const ull*>(&sS0[cur * 32 * SSTR + (w + 16) * SSTR]);
#pragma unroll
                for (int mp = 0; mp < 8; mp++) {
                    ull sA2 = spA[mp];
                    ull sB2 = spB[mp];
#pragma unroll
                    for (int c = 0; c < 4; c++) {
                        FMA2(acc2[mp][c], sA2, eDA[c]);
                        FMA2(acc2[mp][c], sB2, eDB[c]);
                    }
                }
            }
            if (has) {
                float s = 1.0f / (1.0f + __expf(-xn));
                sS0[(cur ^ 1) * 32 * SSTR + vS * SSTR + mS] = s;
                szAcc += (double)s;
            }
            __syncthreads();
            eA = eAn; eB = eBn; cur ^= 1;
        }

        // sizeP: warp w's lanes hold m=w contributions
        {
            double s = szAcc;
#pragma unroll
            for (int k = 16; k; k >>= 1) s += __shfl_xor_sync(0xffffffffu, s, k);
            if (lane == 0) atomicAdd(&g_sizeP[w], s);
        }
        // PhiP reduction across 16 warps
        for (int m = 0; m < 16; m++) {
            const int mp = m >> 1, hi = m & 1;
            __syncthreads();
            float4 v;
            float2 u0 = unpack2(acc2[mp][0]);
            float2 u1 = unpack2(acc2[mp][1]);
            float2 u2 = unpack2(acc2[mp][2]);
            float2 u3 = unpack2(acc2[mp][3]);
            v.x = hi ? u0.y : u0.x; v.y = hi ? u1.y : u1.x;
            v.z = hi ? u2.y : u2.x; v.w = hi ? u3.y : u3.x;
            *reinterpret_cast<float4*>(&sRed[w * 128 + lane * 4]) = v;
            __syncthreads();
            if (t < 128) {
                float s = 0.f;
#pragma unroll
                for (int w2 = 0; w2 < 16; w2++) s += sRed[w2 * 128 + t];
                atomicAdd(&g_PhiP[m * Ac + t], s);
            }
        }
    }
    grid_barrier();

    // ================= P2: nnz gather =================
    {
        const int grp = (bid << 2) | (t >> 7);   // 592 groups
        const int l = t & 127;
        const int nChunks = NNZc / 128;          // 2048
        for (int c = grp; c < nChunks; c += NBLK * 4) {
            const int i0 = c * 128;
            // first segment with qoffs[seg+1] > i0
            int lo = 0, hi = Bc - 1;
            while (lo < hi) { int mid = (lo + hi) >> 1; if (qoffs[mid + 1] <= i0) lo = mid + 1; else hi = mid; }
            int seg = lo;
            int nxt = qoffs[seg + 1];

            float accQ = 0.f;
            double accP = 0.0;
            bool dirty = false;
            const int iend = i0 + 128;
            int i = i0;
            while (i < iend) {
                if (i >= nxt) {
                    if (dirty) {
                        atomicAdd(&g_PhiQ[seg * Ac + l], accQ);
                        if (l < 16) atomicAdd(&g_psum[seg * 16 + l], accP);
                        accQ = 0.f; accP = 0.0; dirty = false;
                    }
                    do { seg++; nxt = qoffs[seg + 1]; } while (i >= nxt);
                }
                int lim = nxt < iend ? nxt : iend;
                int cnt = lim - i;
                dirty = true;
                int k = 0;
                for (; k + 8 <= cnt; k += 8) {
                    int id[8];
#pragma unroll
                    for (int j = 0; j < 8; j++) id[j] = __ldg(&qids[i + k + j]);
                    float a[8];
#pragma unroll
                    for (int j = 0; j < 8; j++) a[j] = atom_emb[(size_t)id[j] * Ac + l];
                    accQ += ((a[0] + a[1]) + (a[2] + a[3])) + ((a[4] + a[5]) + (a[6] + a[7]));
                    if (l < 16) {
                        double s = 0.0;
#pragma unroll
                        for (int j = 0; j < 8; j++) s += (double)g_sigT[(size_t)id[j] * 16 + l];
                        accP += s;
                    }
                }
                for (; k < cnt; k++) {
                    int id = __ldg(&qids[i + k]);
                    accQ += atom_emb[(size_t)id * Ac + l];
                    if (l < 16) accP += (double)g_sigT[(size_t)id * 16 + l];
                }
                i = lim;
            }
            if (dirty) {
                atomicAdd(&g_PhiQ[seg * Ac + l], accQ);
                if (l < 16) atomicAdd(&g_psum[seg * 16 + l], accP);
            }
        }
    }
    grid_barrier();

    // ================= P3a: AQ, BP, Vp =================
    {
        const int ug = (bid << 2) | (t >> 7);    // 592 slots, need 80
        const int l = t & 127;
        if (ug < Bc) {
            int b = ug;
            const float4* pv = reinterpret_cast<const float4*>(&g_PhiQ[b * Ac]);
            const float4* wr = reinterpret_cast<const float4*>(&W_A[l * Ac]);
            float acc = 0.f;
#pragma unroll 16
            for (int a = 0; a < Ac / 4; a++) {
                float4 w4 = wr[a], v4 = pv[a];
                acc += w4.x * v4.x + w4.y * v4.y + w4.z * v4.z + w4.w * v4.w;
            }
            g_AQ[b * Ac + l] = acc;
        } else if (ug < Bc + Mc) {
            int m = ug - Bc;
            const float4* pv = reinterpret_cast<const float4*>(&g_PhiP[m * Ac]);
            const float4* wr = reinterpret_cast<const float4*>(&W_B[l * Ac]);
            float acc = 0.f;
#pragma unroll 16
            for (int a = 0; a < Ac / 4; a++) {
                float4 w4 = wr[a], v4 = pv[a];
                acc += w4.x * v4.x + w4.y * v4.y + w4.z * v4.z + w4.w * v4.w;
            }
            g_BP[m * Ac + l] = acc;
            if (l < HDc) {
                const float4* wv = reinterpret_cast<const float4*>(&W_val[l * Ac]);
                float a2 = 0.f;
#pragma unroll 16
                for (int a = 0; a < Ac / 4; a++) {
                    float4 w4 = wv[a], v4 = pv[a];
                    a2 += w4.x * v4.x + w4.y * v4.y + w4.z * v4.z + w4.w * v4.w;
                }
                g_Vp[m * HDc + l] = a2 + b_val[l];
            }
        }
    }
    grid_barrier();

    // ================= P3b: scores (fp64) -> softmax -> Z (block 0) =================
    if (bid == 0) {
#pragma unroll
        for (int rep = 0; rep < 2; rep++) {
            const int t2 = t + rep * 512;
            const int b = t2 >> 4, m = t2 & 15;
            float dotv = 0.f;
            const float4* aq = reinterpret_cast<const float4*>(&g_AQ[b * Ac]);
            const float4* bp = reinterpret_cast<const float4*>(&g_BP[m * Ac]);
#pragma unroll 8
            for (int i = 0; i < Ac / 4; i++) {
                float4 a4 = aq[i], b4 = bp[i];
                dotv += a4.x * b4.x + a4.y * b4.y + a4.z * b4.z + a4.w * b4.w;
            }
            double szQ = (double)(qoffs[b + 1] - qoffs[b]);
            double szP = g_sizeP[m];
            double delta = szQ + szP - 2.0 * g_psum[b * 16 + m];
            double score = -GAMMAc * delta + BETAc * (double)dotv
                         + (double)size_w[0] * szQ + (double)size_w[1] * szP;
            double mx = score;
#pragma unroll
            for (int k = 8; k; k >>= 1) mx = fmax(mx, __shfl_xor_sync(0xffffffffu, mx, k));
            double e = exp(score - mx);
            double ssum = e;
#pragma unroll
            for (int k = 8; k; k >>= 1) ssum += __shfl_xor_sync(0xffffffffu, ssum, k);
            sAttn[t2] = (float)(e / ssum);
        }
        __syncthreads();
        for (int o = t; o < Bc * HDc; o += 512) {
            int bb = o >> 5, hd = o & 31;
            float z = 0.f;
#pragma unroll
            for (int mm = 0; mm < 16; mm++) z += sAttn[bb * 16 + mm] * g_Vp[mm * HDc + hd];
            g_Z[o] = z;
        }
    }
    grid_barrier();

    // ================= P3c: C[b][d][h] =================
    {
        const int ug = (bid << 2) | (t >> 7);
        const int l = t & 127;
        if (ug < Bc) {
            int b = ug;
            float z[HDc];
            const float4* zp = reinterpret_cast<const float4*>(&g_Z[b * HDc]);
#pragma unroll
            for (int j = 0; j < HDc / 4; j++) {
                float4 z4 = zp[j];
                z[j * 4 + 0] = z4.x; z[j * 4 + 1] = z4.y; z[j * 4 + 2] = z4.z; z[j * 4 + 3] = z4.w;
            }
#pragma unroll
            for (int h = 0; h < Hc; h++) {
                float acc = 0.f;
                const float* wr = &W_out[l * Dc + h * HDc];
#pragma unroll 8
                for (int j = 0; j < HDc; j++) acc += wr[j] * z[j];
                g_C[(b * Dc + l) * Hc + h] = acc;
            }
        }
    }
    grid_barrier();

    // ================= P4: token pass =================
    {
        float4 wg[4];
#pragma unroll
        for (int h = 0; h < 4; h++) wg[h] = *reinterpret_cast<const float4*>(&W_gate[h * Dc + lane * 4]);
        const float bg0 = b_gate[0], bg1 = b_gate[1], bg2 = b_gate[2], bg3 = b_gate[3];
        const float4 bo = *reinterpret_cast<const float4*>(&b_out[lane * 4]);

        for (int u = bid; u < Bc * 8; u += NBLK) {
            const int b = u >> 3, part = u & 7;
            float4 c[4];
#pragma unroll
            for (int j = 0; j < 4; j++) c[j] = *reinterpret_cast<const float4*>(&g_C[(b * Dc + lane * 4 + j) * Hc]);
            const float* xb = ts + (size_t)b * Lc * Dc;
            float* ob = out + (size_t)b * Lc * Dc;
            const int l0 = part * 256 + w * 16;
#pragma unroll 2
            for (int k = 0; k < 16; k++) {
                const int l = l0 + k;
                const float4 x = *reinterpret_cast<const float4*>(&xb[l * Dc + lane * 4]);
                float p0 = x.x * wg[0].x + x.y * wg[0].y + x.z * wg[0].z + x.w * wg[0].w;
                float p1 = x.x * wg[1].x + x.y * wg[1].y + x.z * wg[1].z + x.w * wg[1].w;
                float p2 = x.x * wg[2].x + x.y * wg[2].y + x.z * wg[2].z + x.w * wg[2].w;
                float p3 = x.x * wg[3].x + x.y * wg[3].y + x.z * wg[3].z + x.w * wg[3].w;
#pragma unroll
                for (int s = 16; s; s >>= 1) {
                    p0 += __shfl_xor_sync(0xffffffffu, p0, s);
                    p1 += __shfl_xor_sync(0xffffffffu, p1, s);
                    p2 += __shfl_xor_sync(0xffffffffu, p2, s);
                    p3 += __shfl_xor_sync(0xffffffffu, p3, s);
                }
                p0 += bg0; p1 += bg1; p2 += bg2; p3 += bg3;
                float mx = fmaxf(fmaxf(p0, p1), fmaxf(p2, p3));
                float e0 = __expf(p0 - mx), e1 = __expf(p1 - mx), e2 = __expf(p2 - mx), e3 = __expf(p3 - mx);
                float inv = 1.f / (e0 + e1 + e2 + e3);
                e0 *= inv; e1 *= inv; e2 *= inv; e3 *= inv;
                float4 o;
                o.x = bo.x + e0 * c[0].x + e1 * c[0].y + e2 * c[0].z + e3 * c[0].w;
                o.y = bo.y + e0 * c[1].x + e1 * c[1].y + e2 * c[1].z + e3 * c[1].w;
                o.z = bo.z + e0 * c[2].x + e1 * c[2].y + e2 * c[2].z + e3 * c[2].w;
                o.w = bo.w + e0 * c[3].x + e1 * c[3].y + e2 * c[3].z + e3 * c[3].w;
                *reinterpret_cast<float4*>(&ob[l * Dc + lane * 4]) = o;
            }
        }
    }
}

// ---------------- launcher ----------------
extern "C" void kernel_launch(void* const* d_in, const int* in_sizes, int n_in,
                              void* d_out, int out_size) {
    const float* token_states = (const float*)d_in[0];
    const int*   query_ids    = (const int*)d_in[1];
    const int*   query_offs   = (const int*)d_in[2];
    const float* atom_emb     = (const float*)d_in[3];
    const float* phi_logits   = (const float*)d_in[4];
    const float* W_A          = (const float*)d_in[5];
    const float* W_B          = (const float*)d_in[6];
    const float* W_val        = (const float*)d_in[7];
    const float* b_val        = (const float*)d_in[8];
    const float* W_gate       = (const float*)d_in[9];
    const float* b_gate       = (const float*)d_in[10];
    const float* W_out        = (const float*)d_in[11];
    const float* b_out        = (const float*)d_in[12];
    const float* size_w       = (const float*)d_in[13];
    float* out = (float*)d_out;

    mega<<<NBLK, NTHR>>>(token_states, query_ids, query_offs, atom_emb, phi_logits,
                         W_A, W_B, W_val, b_val, W_gate, b_gate, W_out, b_out,
                         size_w, out);
}